// round 2
// baseline (speedup 1.0000x reference)
#include <cuda_runtime.h>
#include <cstdint>

#define B 64
#define NPRED 25200          // 3*(6400+1600+400) per anchor set: 3*8400
#define TOPK 1024
#define MAXDET 300
#define CONF_THRES 0.25f
#define IOU_THRES 0.45f

// scale layout: scale0: p in [0,19200) nx=80 ; scale1: [19200,24000) nx=40 ; scale2: [24000,25200) nx=20
// within scale: p_local = a*ny*nx + y*nx + x

__device__ unsigned long long g_keys[B * NPRED];   // packed (score_bits<<32)|(~idx)
__device__ unsigned long long g_top[B * TOPK];     // per-image sorted top-1024 keys

__device__ __forceinline__ float sigmoidf(float x) {
    return 1.0f / (1.0f + expf(-x));
}

// ---------------------------------------------------------------------------
// K1: per-candidate score -> sortable key
// ---------------------------------------------------------------------------
__global__ void score_kernel(const float* __restrict__ r0,
                             const float* __restrict__ r1,
                             const float* __restrict__ r2)
{
    int gid = blockIdx.x * blockDim.x + threadIdx.x;
    if (gid >= B * NPRED) return;
    int b = gid / NPRED;
    int p = gid - b * NPRED;

    const float* v;
    if (p < 19200)      v = r0 + (size_t)(b * 19200 + p) * 20;
    else if (p < 24000) v = r1 + (size_t)(b * 4800 + (p - 19200)) * 20;
    else                v = r2 + (size_t)(b * 1200 + (p - 24000)) * 20;

    float obj_raw = v[4];
    float m = v[5];
#pragma unroll
    for (int c = 1; c < 15; ++c) m = fmaxf(m, v[5 + c]);

    float obj  = sigmoidf(obj_raw);
    float best = obj * sigmoidf(m);
    float score = (obj > CONF_THRES && best > CONF_THRES) ? best : 0.0f;

    unsigned long long key =
        ((unsigned long long)__float_as_uint(score) << 32) |
        (unsigned long long)(0xFFFFFFFFu - (unsigned)p);
    g_keys[gid] = key;
}

// ---------------------------------------------------------------------------
// K2: exact per-image top-1024 via bitonic merge top-k (1 block / image)
// ---------------------------------------------------------------------------
__device__ __forceinline__ void bitonic_sort_desc(unsigned long long* a, int t)
{
    for (int k = 2; k <= 1024; k <<= 1) {
        for (int j = k >> 1; j > 0; j >>= 1) {
            int ixj = t ^ j;
            if (ixj > t) {
                unsigned long long u = a[t], w = a[ixj];
                bool desc = ((t & k) == 0);
                if ((u < w) == desc) { a[t] = w; a[ixj] = u; }
            }
            __syncthreads();
        }
    }
}

__device__ __forceinline__ void bitonic_merge_desc(unsigned long long* a, int t)
{
    for (int j = 512; j > 0; j >>= 1) {
        int ixj = t ^ j;
        if (ixj > t) {
            unsigned long long u = a[t], w = a[ixj];
            if (u < w) { a[t] = w; a[ixj] = u; }
        }
        __syncthreads();
    }
}

__global__ __launch_bounds__(1024) void topk_kernel()
{
    __shared__ unsigned long long sTop[1024];
    __shared__ unsigned long long sCh[1024];
    int b = blockIdx.x;
    int t = threadIdx.x;
    const unsigned long long* k = g_keys + (size_t)b * NPRED;

    sTop[t] = k[t];
    __syncthreads();
    bitonic_sort_desc(sTop, t);

    const int NCHUNK = (NPRED + 1023) / 1024;   // 25
    for (int c = 1; c < NCHUNK; ++c) {
        int idx = c * 1024 + t;
        sCh[t] = (idx < NPRED) ? k[idx] : 0ULL;
        __syncthreads();
        bitonic_sort_desc(sCh, t);
        unsigned long long a = sTop[t];
        unsigned long long w = sCh[1023 - t];
        unsigned long long m = (a > w) ? a : w;
        __syncthreads();
        sTop[t] = m;
        __syncthreads();
        bitonic_merge_desc(sTop, t);
    }
    g_top[(size_t)b * TOPK + t] = sTop[t];
}

// ---------------------------------------------------------------------------
// K3: decode selected boxes, greedy NMS, compact top-300 to output
// ---------------------------------------------------------------------------
__global__ __launch_bounds__(1024) void nms_kernel(const float* __restrict__ r0,
                                                   const float* __restrict__ r1,
                                                   const float* __restrict__ r2,
                                                   const float* __restrict__ stride,
                                                   const float* __restrict__ ag,
                                                   float* __restrict__ out)
{
    __shared__ float sx1[1024], sy1[1024], sx2[1024], sy2[1024];
    __shared__ float sar[1024];
    __shared__ int   s_keep[1024];
    __shared__ int   s_wcnt[32];
    __shared__ int   s_woff[32];

    int b = blockIdx.x;
    int t = threadIdx.x;

    unsigned long long key = g_top[(size_t)b * TOPK + t];
    float sc = __uint_as_float((unsigned)(key >> 32));
    unsigned p = 0xFFFFFFFFu - (unsigned)(key & 0xFFFFFFFFu);
    if (p >= NPRED) p = 0;   // safety (cannot happen: 25200 >= 1024 real keys)

    // locate (scale, anchor, gy, gx)
    const float* v;
    float s;
    int scale, a, gy, gx;
    if (p < 19200) {
        scale = 0; int l = p;
        a = l / 6400; int r = l - a * 6400; gy = r / 80; gx = r - gy * 80;
        v = r0 + (size_t)(b * 19200 + l) * 20; s = stride[0];
    } else if (p < 24000) {
        scale = 1; int l = p - 19200;
        a = l / 1600; int r = l - a * 1600; gy = r / 40; gx = r - gy * 40;
        v = r1 + (size_t)(b * 4800 + l) * 20; s = stride[1];
    } else {
        scale = 2; int l = p - 24000;
        a = l / 400; int r = l - a * 400; gy = r / 20; gx = r - gy * 20;
        v = r2 + (size_t)(b * 1200 + l) * 20; s = stride[2];
    }

    float s0 = sigmoidf(v[0]);
    float s1 = sigmoidf(v[1]);
    float s2 = sigmoidf(v[2]);
    float s3 = sigmoidf(v[3]);
    float cx = (s0 * 2.0f - 0.5f + (float)gx) * s;
    float cy = (s1 * 2.0f - 0.5f + (float)gy) * s;
    float tw = s2 * 2.0f;
    float th = s3 * 2.0f;
    float w = tw * tw * ag[scale * 6 + a * 2 + 0];
    float h = th * th * ag[scale * 6 + a * 2 + 1];

    float x1 = cx - w * 0.5f;
    float y1 = cy - h * 0.5f;
    float x2 = cx + w * 0.5f;
    float y2 = cy + h * 0.5f;

    // class argmax (first max, matching jnp.argmax; sigmoid monotone => raw argmax)
    float mv = v[5]; int mc = 0;
#pragma unroll
    for (int c = 1; c < 15; ++c) {
        float cv = v[5 + c];
        if (cv > mv) { mv = cv; mc = c; }
    }

    sx1[t] = x1; sy1[t] = y1; sx2[t] = x2; sy2[t] = y2;
    sar[t] = (x2 - x1) * (y2 - y1);
    s_keep[t] = (sc > CONF_THRES) ? 1 : 0;
    __syncthreads();

    // greedy NMS: sequential over i, parallel over j
    for (int i = 0; i < TOPK; ++i) {
        if (!s_keep[i]) continue;         // uniform: same smem value for all threads
        float bx1 = sx1[i], by1 = sy1[i], bx2 = sx2[i], by2 = sy2[i], ba = sar[i];
        if (t > i && s_keep[t]) {
            float lx = fmaxf(sx1[t], bx1);
            float ly = fmaxf(sy1[t], by1);
            float rx = fminf(sx2[t], bx2);
            float ry = fminf(sy2[t], by2);
            float iw = fmaxf(rx - lx, 0.0f);
            float ih = fmaxf(ry - ly, 0.0f);
            float inter = iw * ih;
            float iou = inter / (sar[t] + ba - inter + 1e-7f);
            if (iou > IOU_THRES) s_keep[t] = 0;
        }
        __syncthreads();
    }

    // rank (stable compaction in array order == reference final top_k order)
    int keepme = s_keep[t];
    unsigned mask = __ballot_sync(0xffffffffu, keepme);
    int lane = t & 31, wid = t >> 5;
    if (lane == 0) s_wcnt[wid] = __popc(mask);
    __syncthreads();
    if (t == 0) {
        int acc = 0;
        for (int wi = 0; wi < 32; ++wi) { s_woff[wi] = acc; acc += s_wcnt[wi]; }
    }
    __syncthreads();
    int rank = s_woff[wid] + __popc(mask & ((1u << lane) - 1u));

    float* outB = out + (size_t)b * MAXDET * 6;
    for (int q = t; q < MAXDET * 6; q += 1024) outB[q] = 0.0f;
    __syncthreads();
    if (keepme && rank < MAXDET) {
        float* r = outB + rank * 6;
        r[0] = x1; r[1] = y1; r[2] = x2; r[3] = y2;
        r[4] = sc; r[5] = (float)mc;
    }
}

// ---------------------------------------------------------------------------
extern "C" void kernel_launch(void* const* d_in, const int* in_sizes, int n_in,
                              void* d_out, int out_size)
{
    const float* r0 = (const float*)d_in[0];
    const float* r1 = (const float*)d_in[1];
    const float* r2 = (const float*)d_in[2];
    const float* stride = (const float*)d_in[3];
    const float* ag = (const float*)d_in[4];
    float* out = (float*)d_out;

    int total = B * NPRED;
    score_kernel<<<(total + 255) / 256, 256>>>(r0, r1, r2);
    topk_kernel<<<B, 1024>>>();
    nms_kernel<<<B, 1024>>>(r0, r1, r2, stride, ag, out);
}

// round 3
// speedup vs baseline: 1.3640x; 1.3640x over previous
#include <cuda_runtime.h>
#include <cstdint>

#define B 64
#define NPRED 25200          // 3*(6400+1600+400) anchors*cells
#define TOPK 1024
#define MAXDET 300
#define CONF_THRES 0.25f
#define IOU_THRES 0.45f
#define NBINS 1024
#define CAP 4096             // smem candidate buffer (keys >= bin threshold)

// valid scores lie in (0.25, 1): fp32 bits in (0x3E800000, 0x3F800000)
// bin = (bits - 0x3E800000) >> 14  ->  [0, 1023], monotone in score
#define BIN_BASE 0x3E800000u

__device__ unsigned long long g_keys[B * NPRED];   // (score_bits<<32)|(~idx)
__device__ unsigned long long g_top[B * TOPK];     // per-image sorted top-1024 keys
__device__ unsigned int       g_hist[B * NBINS];

__device__ __forceinline__ float sigmoidf(float x) {
    return 1.0f / (1.0f + expf(-x));
}

// ---------------------------------------------------------------------------
// K0: zero per-image histograms (device globals persist across graph replays)
// ---------------------------------------------------------------------------
__global__ void zero_hist_kernel()
{
    g_hist[blockIdx.x * NBINS + threadIdx.x] = 0u;
}

// ---------------------------------------------------------------------------
// K1: per-candidate score -> sortable key + score-bin histogram
// ---------------------------------------------------------------------------
__global__ void score_kernel(const float* __restrict__ r0,
                             const float* __restrict__ r1,
                             const float* __restrict__ r2)
{
    int gid = blockIdx.x * blockDim.x + threadIdx.x;
    if (gid >= B * NPRED) return;
    int b = gid / NPRED;
    int p = gid - b * NPRED;

    const float* v;
    if (p < 19200)      v = r0 + (size_t)(b * 19200 + p) * 20;
    else if (p < 24000) v = r1 + (size_t)(b * 4800 + (p - 19200)) * 20;
    else                v = r2 + (size_t)(b * 1200 + (p - 24000)) * 20;

    // records are 80B (16B aligned): floats 4..19 = four float4 loads
    const float4* v4 = (const float4*)v;
    float4 qa = v4[1];   // obj, cls0..2
    float4 qb = v4[2];   // cls3..6
    float4 qc = v4[3];   // cls7..10
    float4 qd = v4[4];   // cls11..14

    float m = qa.y;
    m = fmaxf(m, qa.z); m = fmaxf(m, qa.w);
    m = fmaxf(m, qb.x); m = fmaxf(m, qb.y); m = fmaxf(m, qb.z); m = fmaxf(m, qb.w);
    m = fmaxf(m, qc.x); m = fmaxf(m, qc.y); m = fmaxf(m, qc.z); m = fmaxf(m, qc.w);
    m = fmaxf(m, qd.x); m = fmaxf(m, qd.y); m = fmaxf(m, qd.z); m = fmaxf(m, qd.w);

    float obj  = sigmoidf(qa.x);
    float best = obj * sigmoidf(m);
    bool valid = (obj > CONF_THRES) && (best > CONF_THRES);
    float score = valid ? best : 0.0f;

    if (valid) {
        unsigned bin = (__float_as_uint(score) - BIN_BASE) >> 14;
        atomicAdd(&g_hist[b * NBINS + bin], 1u);
    }

    unsigned long long key =
        ((unsigned long long)__float_as_uint(score) << 32) |
        (unsigned long long)(0xFFFFFFFFu - (unsigned)p);
    g_keys[gid] = key;
}

// ---------------------------------------------------------------------------
// K2: exact per-image top-1024 via radix-select + single bitonic sort
// ---------------------------------------------------------------------------
__device__ __forceinline__ void bitonic_sort_desc_1k(unsigned long long* a, int t)
{
    for (int k = 2; k <= 1024; k <<= 1) {
        for (int j = k >> 1; j > 0; j >>= 1) {
            int ixj = t ^ j;
            if (ixj > t) {
                unsigned long long u = a[t], w = a[ixj];
                bool desc = ((t & k) == 0);
                if ((u < w) == desc) { a[t] = w; a[ixj] = u; }
            }
            __syncthreads();
        }
    }
}

__device__ __forceinline__ void bitonic_merge_desc_1k(unsigned long long* a, int t)
{
    for (int j = 512; j > 0; j >>= 1) {
        int ixj = t ^ j;
        if (ixj > t) {
            unsigned long long u = a[t], w = a[ixj];
            if (u < w) { a[t] = w; a[ixj] = u; }
        }
        __syncthreads();
    }
}

__global__ __launch_bounds__(1024) void topk_select_kernel()
{
    __shared__ unsigned long long sBuf[CAP];         // 32 KB
    __shared__ unsigned int sA[NBINS], sBn[NBINS];   // 8 KB scan ping-pong
    __shared__ int sCut, sCount;

    int b = blockIdx.x;
    int t = threadIdx.x;
    const unsigned long long* k = g_keys + (size_t)b * NPRED;

    // load histogram reversed (index 0 = highest bin) for suffix sums
    sA[t] = g_hist[b * NBINS + (NBINS - 1 - t)];
    if (t == 0) { sCut = 0; sCount = 0; }
    __syncthreads();

    // inclusive scan (Hillis-Steele), 10 steps, ends back in sA
    unsigned int* src = sA;
    unsigned int* dst = sBn;
    for (int off = 1; off < NBINS; off <<= 1) {
        unsigned v = src[t] + ((t >= off) ? src[t - off] : 0u);
        dst[t] = v;
        __syncthreads();
        unsigned int* tmp = src; src = dst; dst = tmp;
    }
    // S(bin) = #valid keys with bin' >= bin = src[NBINS-1-bin]
    {
        unsigned S     = src[NBINS - 1 - t];
        unsigned Snext = (t == NBINS - 1) ? 0u : src[NBINS - 2 - t];
        if (S >= TOPK && Snext < TOPK) sCut = t;   // unique (S non-increasing)
    }
    __syncthreads();
    int cutoff = sCut;
    unsigned long long thresh =
        ((unsigned long long)(BIN_BASE + ((unsigned)cutoff << 14))) << 32;

    // compact all keys >= thresh into smem
    const int NCHUNK = (NPRED + 1023) / 1024;   // 25
    for (int c = 0; c < NCHUNK; ++c) {
        int idx = c * 1024 + t;
        unsigned long long key = (idx < NPRED) ? k[idx] : 0ULL;
        if (key >= thresh) {
            int pos = atomicAdd(&sCount, 1);
            if (pos < CAP) sBuf[pos] = key;
        }
    }
    __syncthreads();
    int n = sCount;   // uniform

    if (n <= CAP) {
        // fast path: single bitonic sort of P in {1024,2048,4096}
        int P = TOPK;
        while (P < n) P <<= 1;
        for (int i = t; i < P; i += 1024)
            if (i >= n) sBuf[i] = 0ULL;
        __syncthreads();

        int E = P >> 10;   // elements per thread
        for (int kk = 2; kk <= P; kk <<= 1) {
            for (int j = kk >> 1; j > 0; j >>= 1) {
                for (int e = 0; e < E; ++e) {
                    int i = e * 1024 + t;
                    int ixj = i ^ j;
                    if (ixj > i) {
                        unsigned long long u = sBuf[i], w = sBuf[ixj];
                        bool desc = ((i & kk) == 0);
                        if ((u < w) == desc) { sBuf[i] = w; sBuf[ixj] = u; }
                    }
                }
                __syncthreads();
            }
        }
        g_top[(size_t)b * TOPK + t] = sBuf[t];
    } else {
        // fallback (should never trigger): exhaustive chunked merge top-k
        unsigned long long* sTop = sBuf;
        unsigned long long* sCh  = sBuf + 1024;
        sTop[t] = k[t];
        __syncthreads();
        bitonic_sort_desc_1k(sTop, t);
        for (int c = 1; c < NCHUNK; ++c) {
            int idx = c * 1024 + t;
            sCh[t] = (idx < NPRED) ? k[idx] : 0ULL;
            __syncthreads();
            bitonic_sort_desc_1k(sCh, t);
            unsigned long long a = sTop[t];
            unsigned long long w = sCh[1023 - t];
            unsigned long long m = (a > w) ? a : w;
            __syncthreads();
            sTop[t] = m;
            __syncthreads();
            bitonic_merge_desc_1k(sTop, t);
        }
        g_top[(size_t)b * TOPK + t] = sTop[t];
    }
}

// ---------------------------------------------------------------------------
// K3: decode selected boxes, greedy NMS, compact top-300 to output
// ---------------------------------------------------------------------------
__global__ __launch_bounds__(1024) void nms_kernel(const float* __restrict__ r0,
                                                   const float* __restrict__ r1,
                                                   const float* __restrict__ r2,
                                                   const float* __restrict__ stride,
                                                   const float* __restrict__ ag,
                                                   float* __restrict__ out)
{
    __shared__ float sx1[1024], sy1[1024], sx2[1024], sy2[1024];
    __shared__ float sar[1024];
    __shared__ int   s_keep[1024];
    __shared__ int   s_wcnt[32];
    __shared__ int   s_woff[32];

    int b = blockIdx.x;
    int t = threadIdx.x;

    unsigned long long key = g_top[(size_t)b * TOPK + t];
    float sc = __uint_as_float((unsigned)(key >> 32));
    unsigned p = 0xFFFFFFFFu - (unsigned)(key & 0xFFFFFFFFu);
    if (p >= NPRED) p = 0;   // safety for zero-padded keys

    const float* v;
    float s;
    int scale, a, gy, gx;
    if (p < 19200) {
        scale = 0; int l = p;
        a = l / 6400; int r = l - a * 6400; gy = r / 80; gx = r - gy * 80;
        v = r0 + (size_t)(b * 19200 + l) * 20; s = stride[0];
    } else if (p < 24000) {
        scale = 1; int l = p - 19200;
        a = l / 1600; int r = l - a * 1600; gy = r / 40; gx = r - gy * 40;
        v = r1 + (size_t)(b * 4800 + l) * 20; s = stride[1];
    } else {
        scale = 2; int l = p - 24000;
        a = l / 400; int r = l - a * 400; gy = r / 20; gx = r - gy * 20;
        v = r2 + (size_t)(b * 1200 + l) * 20; s = stride[2];
    }

    const float4* v4 = (const float4*)v;
    float4 q0 = v4[0];   // raw xywh
    float4 qa = v4[1];   // obj, cls0..2
    float4 qb = v4[2];
    float4 qc = v4[3];
    float4 qd = v4[4];

    float s0 = sigmoidf(q0.x);
    float s1 = sigmoidf(q0.y);
    float s2 = sigmoidf(q0.z);
    float s3 = sigmoidf(q0.w);
    float cx = (s0 * 2.0f - 0.5f + (float)gx) * s;
    float cy = (s1 * 2.0f - 0.5f + (float)gy) * s;
    float tw = s2 * 2.0f;
    float th = s3 * 2.0f;
    float w = tw * tw * ag[scale * 6 + a * 2 + 0];
    float h = th * th * ag[scale * 6 + a * 2 + 1];

    float x1 = cx - w * 0.5f;
    float y1 = cy - h * 0.5f;
    float x2 = cx + w * 0.5f;
    float y2 = cy + h * 0.5f;

    // class argmax (first max, matching jnp.argmax)
    float cls[15] = { qa.y, qa.z, qa.w, qb.x, qb.y, qb.z, qb.w,
                      qc.x, qc.y, qc.z, qc.w, qd.x, qd.y, qd.z, qd.w };
    float mv = cls[0]; int mc = 0;
#pragma unroll
    for (int c = 1; c < 15; ++c)
        if (cls[c] > mv) { mv = cls[c]; mc = c; }

    sx1[t] = x1; sy1[t] = y1; sx2[t] = x2; sy2[t] = y2;
    sar[t] = (x2 - x1) * (y2 - y1);
    s_keep[t] = (sc > CONF_THRES) ? 1 : 0;
    __syncthreads();

    // greedy NMS: sequential over i, parallel over j
    for (int i = 0; i < TOPK; ++i) {
        if (!s_keep[i]) continue;         // uniform read -> uniform branch
        float bx1 = sx1[i], by1 = sy1[i], bx2 = sx2[i], by2 = sy2[i], ba = sar[i];
        if (t > i && s_keep[t]) {
            float lx = fmaxf(sx1[t], bx1);
            float ly = fmaxf(sy1[t], by1);
            float rx = fminf(sx2[t], bx2);
            float ry = fminf(sy2[t], by2);
            float iw = fmaxf(rx - lx, 0.0f);
            float ih = fmaxf(ry - ly, 0.0f);
            float inter = iw * ih;
            float iou = inter / (sar[t] + ba - inter + 1e-7f);
            if (iou > IOU_THRES) s_keep[t] = 0;
        }
        __syncthreads();
    }

    // stable compaction (array order == reference final top_k order)
    int keepme = s_keep[t];
    unsigned mask = __ballot_sync(0xffffffffu, keepme);
    int lane = t & 31, wid = t >> 5;
    if (lane == 0) s_wcnt[wid] = __popc(mask);
    __syncthreads();
    if (t == 0) {
        int acc = 0;
        for (int wi = 0; wi < 32; ++wi) { s_woff[wi] = acc; acc += s_wcnt[wi]; }
    }
    __syncthreads();
    int rank = s_woff[wid] + __popc(mask & ((1u << lane) - 1u));

    float* outB = out + (size_t)b * MAXDET * 6;
    for (int q = t; q < MAXDET * 6; q += 1024) outB[q] = 0.0f;
    __syncthreads();
    if (keepme && rank < MAXDET) {
        float* r = outB + rank * 6;
        r[0] = x1; r[1] = y1; r[2] = x2; r[3] = y2;
        r[4] = sc; r[5] = (float)mc;
    }
}

// ---------------------------------------------------------------------------
extern "C" void kernel_launch(void* const* d_in, const int* in_sizes, int n_in,
                              void* d_out, int out_size)
{
    const float* r0 = (const float*)d_in[0];
    const float* r1 = (const float*)d_in[1];
    const float* r2 = (const float*)d_in[2];
    const float* stride = (const float*)d_in[3];
    const float* ag = (const float*)d_in[4];
    float* out = (float*)d_out;

    int total = B * NPRED;
    zero_hist_kernel<<<B, NBINS>>>();
    score_kernel<<<(total + 255) / 256, 256>>>(r0, r1, r2);
    topk_select_kernel<<<B, 1024>>>();
    nms_kernel<<<B, 1024>>>(r0, r1, r2, stride, ag, out);
}

// round 4
// speedup vs baseline: 1.7830x; 1.3072x over previous
#include <cuda_runtime.h>
#include <cstdint>

#define B 64
#define NPRED 25200          // 3*(6400+1600+400) anchors*cells
#define TOPK 1024
#define MAXDET 300
#define CONF_THRES 0.25f
#define IOU_THRES 0.45f
#define NBINS 1024
#define CAP 4096             // smem candidate buffer (keys >= bin threshold)

// valid scores lie in (0.25, 1): fp32 bits in (0x3E800000, 0x3F800000)
#define BIN_BASE 0x3E800000u

__device__ unsigned long long g_keys[B * NPRED];   // (score_bits<<32)|(~idx)
__device__ unsigned long long g_top[B * TOPK];     // per-image sorted top-1024 keys
__device__ unsigned int       g_hist[B * NBINS];

// candidate SoA (decoded boxes for the 1024 selected per image)
__device__ float g_bx1[B * TOPK];
__device__ float g_by1[B * TOPK];
__device__ float g_bx2[B * TOPK];
__device__ float g_by2[B * TOPK];
__device__ float g_bar[B * TOPK];
__device__ float g_bsc[B * TOPK];
__device__ float g_bcl[B * TOPK];
__device__ unsigned g_active[B * 32];              // active bit per candidate

// suppression bitmatrix: g_mask[b][i][w] bit jj -> i suppresses j=w*32+jj (j>i only)
__device__ unsigned g_mask[B * TOPK * 32];         // 8 MB

__device__ __forceinline__ float sigmoidf(float x) {
    return 1.0f / (1.0f + expf(-x));
}

// ---------------------------------------------------------------------------
// K0: zero per-image histograms
// ---------------------------------------------------------------------------
__global__ void zero_hist_kernel()
{
    g_hist[blockIdx.x * NBINS + threadIdx.x] = 0u;
}

// ---------------------------------------------------------------------------
// K1: per-candidate score -> sortable key + score-bin histogram
// ---------------------------------------------------------------------------
__global__ void score_kernel(const float* __restrict__ r0,
                             const float* __restrict__ r1,
                             const float* __restrict__ r2)
{
    int gid = blockIdx.x * blockDim.x + threadIdx.x;
    if (gid >= B * NPRED) return;
    int b = gid / NPRED;
    int p = gid - b * NPRED;

    const float* v;
    if (p < 19200)      v = r0 + (size_t)(b * 19200 + p) * 20;
    else if (p < 24000) v = r1 + (size_t)(b * 4800 + (p - 19200)) * 20;
    else                v = r2 + (size_t)(b * 1200 + (p - 24000)) * 20;

    const float4* v4 = (const float4*)v;
    float4 qa = v4[1];   // obj, cls0..2
    float4 qb = v4[2];
    float4 qc = v4[3];
    float4 qd = v4[4];

    float m = qa.y;
    m = fmaxf(m, qa.z); m = fmaxf(m, qa.w);
    m = fmaxf(m, qb.x); m = fmaxf(m, qb.y); m = fmaxf(m, qb.z); m = fmaxf(m, qb.w);
    m = fmaxf(m, qc.x); m = fmaxf(m, qc.y); m = fmaxf(m, qc.z); m = fmaxf(m, qc.w);
    m = fmaxf(m, qd.x); m = fmaxf(m, qd.y); m = fmaxf(m, qd.z); m = fmaxf(m, qd.w);

    float obj  = sigmoidf(qa.x);
    float best = obj * sigmoidf(m);
    bool valid = (obj > CONF_THRES) && (best > CONF_THRES);
    float score = valid ? best : 0.0f;

    if (valid) {
        unsigned bin = (__float_as_uint(score) - BIN_BASE) >> 14;
        atomicAdd(&g_hist[b * NBINS + bin], 1u);
    }

    unsigned long long key =
        ((unsigned long long)__float_as_uint(score) << 32) |
        (unsigned long long)(0xFFFFFFFFu - (unsigned)p);
    g_keys[gid] = key;
}

// ---------------------------------------------------------------------------
// K2: exact per-image top-1024 via radix-select + single bitonic sort
// ---------------------------------------------------------------------------
__device__ __forceinline__ void bitonic_sort_desc_1k(unsigned long long* a, int t)
{
    for (int k = 2; k <= 1024; k <<= 1) {
        for (int j = k >> 1; j > 0; j >>= 1) {
            int ixj = t ^ j;
            if (ixj > t) {
                unsigned long long u = a[t], w = a[ixj];
                bool desc = ((t & k) == 0);
                if ((u < w) == desc) { a[t] = w; a[ixj] = u; }
            }
            __syncthreads();
        }
    }
}

__device__ __forceinline__ void bitonic_merge_desc_1k(unsigned long long* a, int t)
{
    for (int j = 512; j > 0; j >>= 1) {
        int ixj = t ^ j;
        if (ixj > t) {
            unsigned long long u = a[t], w = a[ixj];
            if (u < w) { a[t] = w; a[ixj] = u; }
        }
        __syncthreads();
    }
}

__global__ __launch_bounds__(1024) void topk_select_kernel()
{
    __shared__ unsigned long long sBuf[CAP];         // 32 KB
    __shared__ unsigned int sA[NBINS], sBn[NBINS];   // 8 KB scan ping-pong
    __shared__ int sCut, sCount;

    int b = blockIdx.x;
    int t = threadIdx.x;
    const unsigned long long* k = g_keys + (size_t)b * NPRED;

    sA[t] = g_hist[b * NBINS + (NBINS - 1 - t)];
    if (t == 0) { sCut = 0; sCount = 0; }
    __syncthreads();

    unsigned int* src = sA;
    unsigned int* dst = sBn;
    for (int off = 1; off < NBINS; off <<= 1) {
        unsigned v = src[t] + ((t >= off) ? src[t - off] : 0u);
        dst[t] = v;
        __syncthreads();
        unsigned int* tmp = src; src = dst; dst = tmp;
    }
    {
        unsigned S     = src[NBINS - 1 - t];
        unsigned Snext = (t == NBINS - 1) ? 0u : src[NBINS - 2 - t];
        if (S >= TOPK && Snext < TOPK) sCut = t;
    }
    __syncthreads();
    int cutoff = sCut;
    unsigned long long thresh =
        ((unsigned long long)(BIN_BASE + ((unsigned)cutoff << 14))) << 32;

    const int NCHUNK = (NPRED + 1023) / 1024;   // 25
    for (int c = 0; c < NCHUNK; ++c) {
        int idx = c * 1024 + t;
        unsigned long long key = (idx < NPRED) ? k[idx] : 0ULL;
        if (key >= thresh) {
            int pos = atomicAdd(&sCount, 1);
            if (pos < CAP) sBuf[pos] = key;
        }
    }
    __syncthreads();
    int n = sCount;

    if (n <= CAP) {
        int P = TOPK;
        while (P < n) P <<= 1;
        for (int i = t; i < P; i += 1024)
            if (i >= n) sBuf[i] = 0ULL;
        __syncthreads();

        int E = P >> 10;
        for (int kk = 2; kk <= P; kk <<= 1) {
            for (int j = kk >> 1; j > 0; j >>= 1) {
                for (int e = 0; e < E; ++e) {
                    int i = e * 1024 + t;
                    int ixj = i ^ j;
                    if (ixj > i) {
                        unsigned long long u = sBuf[i], w = sBuf[ixj];
                        bool desc = ((i & kk) == 0);
                        if ((u < w) == desc) { sBuf[i] = w; sBuf[ixj] = u; }
                    }
                }
                __syncthreads();
            }
        }
        g_top[(size_t)b * TOPK + t] = sBuf[t];
    } else {
        unsigned long long* sTop = sBuf;
        unsigned long long* sCh  = sBuf + 1024;
        sTop[t] = k[t];
        __syncthreads();
        bitonic_sort_desc_1k(sTop, t);
        for (int c = 1; c < NCHUNK; ++c) {
            int idx = c * 1024 + t;
            sCh[t] = (idx < NPRED) ? k[idx] : 0ULL;
            __syncthreads();
            bitonic_sort_desc_1k(sCh, t);
            unsigned long long a = sTop[t];
            unsigned long long w = sCh[1023 - t];
            unsigned long long m = (a > w) ? a : w;
            __syncthreads();
            sTop[t] = m;
            __syncthreads();
            bitonic_merge_desc_1k(sTop, t);
        }
        g_top[(size_t)b * TOPK + t] = sTop[t];
    }
}

// ---------------------------------------------------------------------------
// K3a: decode the 1024 selected candidates per image -> global SoA
// ---------------------------------------------------------------------------
__global__ __launch_bounds__(1024) void decode_kernel(const float* __restrict__ r0,
                                                      const float* __restrict__ r1,
                                                      const float* __restrict__ r2,
                                                      const float* __restrict__ stride,
                                                      const float* __restrict__ ag)
{
    int b = blockIdx.x;
    int t = threadIdx.x;
    int g = b * TOPK + t;

    unsigned long long key = g_top[(size_t)g];
    float sc = __uint_as_float((unsigned)(key >> 32));
    unsigned p = 0xFFFFFFFFu - (unsigned)(key & 0xFFFFFFFFu);
    if (p >= NPRED) p = 0;

    const float* v;
    float s;
    int scale, a, gy, gx;
    if (p < 19200) {
        scale = 0; int l = p;
        a = l / 6400; int r = l - a * 6400; gy = r / 80; gx = r - gy * 80;
        v = r0 + (size_t)(b * 19200 + l) * 20; s = stride[0];
    } else if (p < 24000) {
        scale = 1; int l = p - 19200;
        a = l / 1600; int r = l - a * 1600; gy = r / 40; gx = r - gy * 40;
        v = r1 + (size_t)(b * 4800 + l) * 20; s = stride[1];
    } else {
        scale = 2; int l = p - 24000;
        a = l / 400; int r = l - a * 400; gy = r / 20; gx = r - gy * 20;
        v = r2 + (size_t)(b * 1200 + l) * 20; s = stride[2];
    }

    const float4* v4 = (const float4*)v;
    float4 q0 = v4[0];
    float4 qa = v4[1];
    float4 qb = v4[2];
    float4 qc = v4[3];
    float4 qd = v4[4];

    float s0 = sigmoidf(q0.x);
    float s1 = sigmoidf(q0.y);
    float s2 = sigmoidf(q0.z);
    float s3 = sigmoidf(q0.w);
    float cx = (s0 * 2.0f - 0.5f + (float)gx) * s;
    float cy = (s1 * 2.0f - 0.5f + (float)gy) * s;
    float tw = s2 * 2.0f;
    float th = s3 * 2.0f;
    float w = tw * tw * ag[scale * 6 + a * 2 + 0];
    float h = th * th * ag[scale * 6 + a * 2 + 1];

    float x1 = cx - w * 0.5f;
    float y1 = cy - h * 0.5f;
    float x2 = cx + w * 0.5f;
    float y2 = cy + h * 0.5f;

    float cls[15] = { qa.y, qa.z, qa.w, qb.x, qb.y, qb.z, qb.w,
                      qc.x, qc.y, qc.z, qc.w, qd.x, qd.y, qd.z, qd.w };
    float mv = cls[0]; int mc = 0;
#pragma unroll
    for (int c = 1; c < 15; ++c)
        if (cls[c] > mv) { mv = cls[c]; mc = c; }

    g_bx1[g] = x1; g_by1[g] = y1; g_bx2[g] = x2; g_by2[g] = y2;
    g_bar[g] = (x2 - x1) * (y2 - y1);
    g_bsc[g] = sc; g_bcl[g] = (float)mc;

    int act = (sc > CONF_THRES) ? 1 : 0;
    unsigned ballot = __ballot_sync(0xffffffffu, act);
    if ((t & 31) == 0) g_active[b * 32 + (t >> 5)] = ballot;
}

// ---------------------------------------------------------------------------
// K3b: suppression bitmatrix (parallel over 256 blocks)
// thread = row i; writes words w >= i>>5 only (diagonal word masked to j>i)
// ---------------------------------------------------------------------------
__global__ __launch_bounds__(256) void mask_kernel()
{
    __shared__ float sx1[TOPK], sy1[TOPK], sx2[TOPK], sy2[TOPK], sar[TOPK];

    int b = blockIdx.y;
    int i = blockIdx.x * 256 + threadIdx.x;
    int base = b * TOPK;

    for (int idx = threadIdx.x; idx < TOPK; idx += 256) {
        sx1[idx] = g_bx1[base + idx];
        sy1[idx] = g_by1[base + idx];
        sx2[idx] = g_bx2[base + idx];
        sy2[idx] = g_by2[base + idx];
        sar[idx] = g_bar[base + idx];
    }
    __syncthreads();

    float bx1 = sx1[i], by1 = sy1[i], bx2 = sx2[i], by2 = sy2[i], ba = sar[i];
    int wstart = i >> 5;
    unsigned* mrow = g_mask + ((size_t)base + i) * 32;

    for (int w = wstart; w < 32; ++w) {
        unsigned bits = 0;
#pragma unroll
        for (int jj = 0; jj < 32; ++jj) {
            int j = w * 32 + jj;
            float lx = fmaxf(bx1, sx1[j]);
            float ly = fmaxf(by1, sy1[j]);
            float rx = fminf(bx2, sx2[j]);
            float ry = fminf(by2, sy2[j]);
            float iw = fmaxf(rx - lx, 0.0f);
            float ih = fmaxf(ry - ly, 0.0f);
            float inter = iw * ih;
            float iou = inter / (ba + sar[j] - inter + 1e-7f);
            if (iou > IOU_THRES) bits |= (1u << jj);
        }
        if (w == wstart) bits &= ~((2u << (i & 31)) - 1u);   // keep only j > i
        mrow[w] = bits;
    }
}

// ---------------------------------------------------------------------------
// K3c: serial greedy reduction (warp 0) + compaction + output
// ---------------------------------------------------------------------------
__global__ __launch_bounds__(1024) void greedy_out_kernel(float* __restrict__ out)
{
    __shared__ unsigned s_keepw[32];
    __shared__ int s_woff[32];

    int b = blockIdx.x;
    int t = threadIdx.x;
    int lane = t & 31, wid = t >> 5;

    if (wid == 0) {
        const unsigned* m = g_mask + (size_t)b * TOPK * 32 + lane;
        unsigned activew = g_active[b * 32 + lane];
        unsigned removed = 0;
        unsigned buf[8];
#pragma unroll
        for (int q = 0; q < 8; ++q) buf[q] = m[q * 32];

        for (int i = 0; i < TOPK; i += 8) {
#pragma unroll
            for (int q = 0; q < 8; ++q) {
                unsigned word = buf[q];
                int ii = i + q;
                int nx = ii + 8;
                buf[q] = (nx < TOPK) ? m[nx * 32] : 0u;   // prefetch (off-chain)
                int ow = ii >> 5;
                unsigned rw = __shfl_sync(0xffffffffu, removed, ow);
                unsigned aw = __shfl_sync(0xffffffffu, activew, ow);
                bool kept = ((aw >> (ii & 31)) & 1u) && !((rw >> (ii & 31)) & 1u);
                if (kept && lane >= ow) removed |= word;
            }
        }
        s_keepw[lane] = activew & ~removed;
    }
    __syncthreads();

    if (t == 0) {
        int acc = 0;
        for (int w = 0; w < 32; ++w) { s_woff[w] = acc; acc += __popc(s_keepw[w]); }
    }
    __syncthreads();

    int keepme = (s_keepw[wid] >> lane) & 1;
    int rank = s_woff[wid] + __popc(s_keepw[wid] & ((1u << lane) - 1u));

    float* outB = out + (size_t)b * MAXDET * 6;
    for (int q = t; q < MAXDET * 6; q += 1024) outB[q] = 0.0f;
    __syncthreads();

    if (keepme && rank < MAXDET) {
        int g = b * TOPK + t;
        float* r = outB + rank * 6;
        r[0] = g_bx1[g]; r[1] = g_by1[g]; r[2] = g_bx2[g]; r[3] = g_by2[g];
        r[4] = g_bsc[g]; r[5] = g_bcl[g];
    }
}

// ---------------------------------------------------------------------------
extern "C" void kernel_launch(void* const* d_in, const int* in_sizes, int n_in,
                              void* d_out, int out_size)
{
    const float* r0 = (const float*)d_in[0];
    const float* r1 = (const float*)d_in[1];
    const float* r2 = (const float*)d_in[2];
    const float* stride = (const float*)d_in[3];
    const float* ag = (const float*)d_in[4];
    float* out = (float*)d_out;

    int total = B * NPRED;
    zero_hist_kernel<<<B, NBINS>>>();
    score_kernel<<<(total + 255) / 256, 256>>>(r0, r1, r2);
    topk_select_kernel<<<B, 1024>>>();
    decode_kernel<<<B, 1024>>>(r0, r1, r2, stride, ag);
    mask_kernel<<<dim3(4, B), 256>>>();
    greedy_out_kernel<<<B, 1024>>>(out);
}

// round 6
// speedup vs baseline: 3.4825x; 1.9531x over previous
#include <cuda_runtime.h>
#include <cstdint>

#define B 64
#define NPRED 25200          // 3*(6400+1600+400) anchors*cells
#define TOPK 1024
#define MAXDET 300
#define CONF_THRES 0.25f
#define IOU_THRES 0.45f
#define NBINS 1024
#define CAP 4096             // smem candidate buffer (keys >= bin threshold)

// valid scores lie in (0.25, 1): fp32 bits in (0x3E800000, 0x3F800000)
#define BIN_BASE 0x3E800000u

__device__ unsigned long long g_keys[B * NPRED];   // (score_bits<<32)|(~idx)
__device__ unsigned long long g_top[B * TOPK];     // per-image sorted top-1024 keys
__device__ unsigned int       g_hist[B * NBINS];

// candidate SoA (decoded boxes for the 1024 selected per image)
__device__ float g_bx1[B * TOPK];
__device__ float g_by1[B * TOPK];
__device__ float g_bx2[B * TOPK];
__device__ float g_by2[B * TOPK];
__device__ float g_bar[B * TOPK];
__device__ float g_bsc[B * TOPK];
__device__ float g_bcl[B * TOPK];
__device__ unsigned g_active[B * 32];              // active bit per candidate

// suppression bitmatrix: g_mask[b][i][w] bit jj -> i suppresses j=w*32+jj (j>i only)
__device__ unsigned g_mask[B * TOPK * 32];         // 8.4 MB

__device__ __forceinline__ float sigmoidf(float x) {
    return 1.0f / (1.0f + expf(-x));
}

// ---------------------------------------------------------------------------
// K0: zero per-image histograms
// ---------------------------------------------------------------------------
__global__ void zero_hist_kernel()
{
    g_hist[blockIdx.x * NBINS + threadIdx.x] = 0u;
}

// ---------------------------------------------------------------------------
// K1: per-candidate score -> sortable key + score-bin histogram
// ---------------------------------------------------------------------------
__global__ void score_kernel(const float* __restrict__ r0,
                             const float* __restrict__ r1,
                             const float* __restrict__ r2)
{
    int gid = blockIdx.x * blockDim.x + threadIdx.x;
    if (gid >= B * NPRED) return;
    int b = gid / NPRED;
    int p = gid - b * NPRED;

    const float* v;
    if (p < 19200)      v = r0 + (size_t)(b * 19200 + p) * 20;
    else if (p < 24000) v = r1 + (size_t)(b * 4800 + (p - 19200)) * 20;
    else                v = r2 + (size_t)(b * 1200 + (p - 24000)) * 20;

    const float4* v4 = (const float4*)v;
    float4 qa = v4[1];   // obj, cls0..2
    float4 qb = v4[2];
    float4 qc = v4[3];
    float4 qd = v4[4];

    float m = qa.y;
    m = fmaxf(m, qa.z); m = fmaxf(m, qa.w);
    m = fmaxf(m, qb.x); m = fmaxf(m, qb.y); m = fmaxf(m, qb.z); m = fmaxf(m, qb.w);
    m = fmaxf(m, qc.x); m = fmaxf(m, qc.y); m = fmaxf(m, qc.z); m = fmaxf(m, qc.w);
    m = fmaxf(m, qd.x); m = fmaxf(m, qd.y); m = fmaxf(m, qd.z); m = fmaxf(m, qd.w);

    float obj  = sigmoidf(qa.x);
    float best = obj * sigmoidf(m);
    bool valid = (obj > CONF_THRES) && (best > CONF_THRES);
    float score = valid ? best : 0.0f;

    if (valid) {
        unsigned bin = (__float_as_uint(score) - BIN_BASE) >> 14;
        atomicAdd(&g_hist[b * NBINS + bin], 1u);
    }

    unsigned long long key =
        ((unsigned long long)__float_as_uint(score) << 32) |
        (unsigned long long)(0xFFFFFFFFu - (unsigned)p);
    g_keys[gid] = key;
}

// ---------------------------------------------------------------------------
// K2: exact per-image top-1024 via radix-select + single bitonic sort
// ---------------------------------------------------------------------------
__device__ __forceinline__ void bitonic_sort_desc_1k(unsigned long long* a, int t)
{
    for (int k = 2; k <= 1024; k <<= 1) {
        for (int j = k >> 1; j > 0; j >>= 1) {
            int ixj = t ^ j;
            if (ixj > t) {
                unsigned long long u = a[t], w = a[ixj];
                bool desc = ((t & k) == 0);
                if ((u < w) == desc) { a[t] = w; a[ixj] = u; }
            }
            __syncthreads();
        }
    }
}

__device__ __forceinline__ void bitonic_merge_desc_1k(unsigned long long* a, int t)
{
    for (int j = 512; j > 0; j >>= 1) {
        int ixj = t ^ j;
        if (ixj > t) {
            unsigned long long u = a[t], w = a[ixj];
            if (u < w) { a[t] = w; a[ixj] = u; }
        }
        __syncthreads();
    }
}

__global__ __launch_bounds__(1024) void topk_select_kernel()
{
    __shared__ unsigned long long sBuf[CAP];         // 32 KB
    __shared__ unsigned int sA[NBINS], sBn[NBINS];   // 8 KB scan ping-pong
    __shared__ int sCut, sCount;

    int b = blockIdx.x;
    int t = threadIdx.x;
    const unsigned long long* k = g_keys + (size_t)b * NPRED;

    sA[t] = g_hist[b * NBINS + (NBINS - 1 - t)];
    if (t == 0) { sCut = 0; sCount = 0; }
    __syncthreads();

    unsigned int* src = sA;
    unsigned int* dst = sBn;
    for (int off = 1; off < NBINS; off <<= 1) {
        unsigned v = src[t] + ((t >= off) ? src[t - off] : 0u);
        dst[t] = v;
        __syncthreads();
        unsigned int* tmp = src; src = dst; dst = tmp;
    }
    {
        unsigned S     = src[NBINS - 1 - t];
        unsigned Snext = (t == NBINS - 1) ? 0u : src[NBINS - 2 - t];
        if (S >= TOPK && Snext < TOPK) sCut = t;
    }
    __syncthreads();
    int cutoff = sCut;
    unsigned long long thresh =
        ((unsigned long long)(BIN_BASE + ((unsigned)cutoff << 14))) << 32;

    const int NCHUNK = (NPRED + 1023) / 1024;   // 25
    for (int c = 0; c < NCHUNK; ++c) {
        int idx = c * 1024 + t;
        unsigned long long key = (idx < NPRED) ? k[idx] : 0ULL;
        if (key >= thresh) {
            int pos = atomicAdd(&sCount, 1);
            if (pos < CAP) sBuf[pos] = key;
        }
    }
    __syncthreads();
    int n = sCount;

    if (n <= CAP) {
        int P = TOPK;
        while (P < n) P <<= 1;
        for (int i = t; i < P; i += 1024)
            if (i >= n) sBuf[i] = 0ULL;
        __syncthreads();

        int E = P >> 10;
        for (int kk = 2; kk <= P; kk <<= 1) {
            for (int j = kk >> 1; j > 0; j >>= 1) {
                for (int e = 0; e < E; ++e) {
                    int i = e * 1024 + t;
                    int ixj = i ^ j;
                    if (ixj > i) {
                        unsigned long long u = sBuf[i], w = sBuf[ixj];
                        bool desc = ((i & kk) == 0);
                        if ((u < w) == desc) { sBuf[i] = w; sBuf[ixj] = u; }
                    }
                }
                __syncthreads();
            }
        }
        g_top[(size_t)b * TOPK + t] = sBuf[t];
    } else {
        unsigned long long* sTop = sBuf;
        unsigned long long* sCh  = sBuf + 1024;
        sTop[t] = k[t];
        __syncthreads();
        bitonic_sort_desc_1k(sTop, t);
        for (int c = 1; c < NCHUNK; ++c) {
            int idx = c * 1024 + t;
            sCh[t] = (idx < NPRED) ? k[idx] : 0ULL;
            __syncthreads();
            bitonic_sort_desc_1k(sCh, t);
            unsigned long long a = sTop[t];
            unsigned long long w = sCh[1023 - t];
            unsigned long long m = (a > w) ? a : w;
            __syncthreads();
            sTop[t] = m;
            __syncthreads();
            bitonic_merge_desc_1k(sTop, t);
        }
        g_top[(size_t)b * TOPK + t] = sTop[t];
    }
}

// ---------------------------------------------------------------------------
// K3a: decode the 1024 selected candidates per image -> global SoA
// ---------------------------------------------------------------------------
__global__ __launch_bounds__(1024) void decode_kernel(const float* __restrict__ r0,
                                                      const float* __restrict__ r1,
                                                      const float* __restrict__ r2,
                                                      const float* __restrict__ stride,
                                                      const float* __restrict__ ag)
{
    int b = blockIdx.x;
    int t = threadIdx.x;
    int g = b * TOPK + t;

    unsigned long long key = g_top[(size_t)g];
    float sc = __uint_as_float((unsigned)(key >> 32));
    unsigned p = 0xFFFFFFFFu - (unsigned)(key & 0xFFFFFFFFu);
    if (p >= NPRED) p = 0;

    const float* v;
    float s;
    int scale, a, gy, gx;
    if (p < 19200) {
        scale = 0; int l = p;
        a = l / 6400; int r = l - a * 6400; gy = r / 80; gx = r - gy * 80;
        v = r0 + (size_t)(b * 19200 + l) * 20; s = stride[0];
    } else if (p < 24000) {
        scale = 1; int l = p - 19200;
        a = l / 1600; int r = l - a * 1600; gy = r / 40; gx = r - gy * 40;
        v = r1 + (size_t)(b * 4800 + l) * 20; s = stride[1];
    } else {
        scale = 2; int l = p - 24000;
        a = l / 400; int r = l - a * 400; gy = r / 20; gx = r - gy * 20;
        v = r2 + (size_t)(b * 1200 + l) * 20; s = stride[2];
    }

    const float4* v4 = (const float4*)v;
    float4 q0 = v4[0];
    float4 qa = v4[1];
    float4 qb = v4[2];
    float4 qc = v4[3];
    float4 qd = v4[4];

    float s0 = sigmoidf(q0.x);
    float s1 = sigmoidf(q0.y);
    float s2 = sigmoidf(q0.z);
    float s3 = sigmoidf(q0.w);
    float cx = (s0 * 2.0f - 0.5f + (float)gx) * s;
    float cy = (s1 * 2.0f - 0.5f + (float)gy) * s;
    float tw = s2 * 2.0f;
    float th = s3 * 2.0f;
    float w = tw * tw * ag[scale * 6 + a * 2 + 0];
    float h = th * th * ag[scale * 6 + a * 2 + 1];

    float x1 = cx - w * 0.5f;
    float y1 = cy - h * 0.5f;
    float x2 = cx + w * 0.5f;
    float y2 = cy + h * 0.5f;

    float cls[15] = { qa.y, qa.z, qa.w, qb.x, qb.y, qb.z, qb.w,
                      qc.x, qc.y, qc.z, qc.w, qd.x, qd.y, qd.z, qd.w };
    float mv = cls[0]; int mc = 0;
#pragma unroll
    for (int c = 1; c < 15; ++c)
        if (cls[c] > mv) { mv = cls[c]; mc = c; }

    g_bx1[g] = x1; g_by1[g] = y1; g_bx2[g] = x2; g_by2[g] = y2;
    g_bar[g] = (x2 - x1) * (y2 - y1);
    g_bsc[g] = sc; g_bcl[g] = (float)mc;

    int act = (sc > CONF_THRES) ? 1 : 0;
    unsigned ballot = __ballot_sync(0xffffffffu, act);
    if ((t & 31) == 0) g_active[b * 32 + (t >> 5)] = ballot;
}

// ---------------------------------------------------------------------------
// K3b: suppression bitmatrix, division-free, balanced, 2x row split
// grid (8, B), 256 threads; work item u = t*8 + x covers (row = u>>1, half = u&1)
// half 0/1 each take ~half of the row's word range [wstart, 32)
// ---------------------------------------------------------------------------
__global__ __launch_bounds__(256) void mask_kernel()
{
    __shared__ float sx1[TOPK], sy1[TOPK], sx2[TOPK], sy2[TOPK], sar[TOPK];

    int b = blockIdx.y;
    int x = blockIdx.x;          // 0..7
    int t = threadIdx.x;         // 0..255
    int base = b * TOPK;

    for (int idx = t; idx < TOPK; idx += 256) {
        sx1[idx] = g_bx1[base + idx];
        sy1[idx] = g_by1[base + idx];
        sx2[idx] = g_bx2[base + idx];
        sy2[idx] = g_by2[base + idx];
        sar[idx] = g_bar[base + idx];
    }
    __syncthreads();

    int u = t * 8 + x;           // balanced: rows strided by 4 within each block
    int i = u >> 1;
    int half = u & 1;            // uniform per block (== x&1)

    float bx1 = sx1[i], by1 = sy1[i], bx2 = sx2[i], by2 = sy2[i], ba = sar[i];
    int wstart = i >> 5;
    int nw = 32 - wstart;
    int nfirst = (nw + 1) >> 1;
    int wlo = half ? (wstart + nfirst) : wstart;
    int whi = half ? 32 : (wstart + nfirst);
    unsigned* mrow = g_mask + ((size_t)base + i) * 32;

    for (int w = wlo; w < whi; ++w) {
        unsigned bits = 0;
#pragma unroll
        for (int jj = 0; jj < 32; ++jj) {
            int j = w * 32 + jj;
            float lx = fmaxf(bx1, sx1[j]);
            float ly = fmaxf(by1, sy1[j]);
            float rx = fminf(bx2, sx2[j]);
            float ry = fminf(by2, sy2[j]);
            float iw = fmaxf(rx - lx, 0.0f);
            float ih = fmaxf(ry - ly, 0.0f);
            float inter = iw * ih;
            // iou > T  <=>  inter > T * U   (U > 0 always)
            float U = ba + sar[j];
            U = U - inter;
            U = U + 1e-7f;
            if (inter > IOU_THRES * U) bits |= (1u << jj);
        }
        if (w == wstart) bits &= ~((2u << (i & 31)) - 1u);   // keep only j > i
        mrow[w] = bits;
    }
}

// ---------------------------------------------------------------------------
// K3c: serial greedy reduction (warp 0) + compaction + output
// ---------------------------------------------------------------------------
__global__ __launch_bounds__(1024) void greedy_out_kernel(float* __restrict__ out)
{
    __shared__ unsigned s_keepw[32];
    __shared__ int s_woff[32];

    int b = blockIdx.x;
    int t = threadIdx.x;
    int lane = t & 31, wid = t >> 5;

    if (wid == 0) {
        const unsigned* m = g_mask + (size_t)b * TOPK * 32 + lane;
        unsigned activew = g_active[b * 32 + lane];
        unsigned removed = 0;
        unsigned buf[8];
#pragma unroll
        for (int q = 0; q < 8; ++q) buf[q] = m[q * 32];

        for (int i = 0; i < TOPK; i += 8) {
#pragma unroll
            for (int q = 0; q < 8; ++q) {
                unsigned word = buf[q];
                int ii = i + q;
                int nx = ii + 8;
                buf[q] = (nx < TOPK) ? m[nx * 32] : 0u;   // prefetch (off-chain)
                int ow = ii >> 5;
                unsigned rw = __shfl_sync(0xffffffffu, removed, ow);
                unsigned aw = __shfl_sync(0xffffffffu, activew, ow);
                bool kept = ((aw >> (ii & 31)) & 1u) && !((rw >> (ii & 31)) & 1u);
                if (kept && lane >= ow) removed |= word;
            }
        }
        s_keepw[lane] = activew & ~removed;
    }
    __syncthreads();

    if (t == 0) {
        int acc = 0;
        for (int w = 0; w < 32; ++w) { s_woff[w] = acc; acc += __popc(s_keepw[w]); }
    }
    __syncthreads();

    int keepme = (s_keepw[wid] >> lane) & 1;
    int rank = s_woff[wid] + __popc(s_keepw[wid] & ((1u << lane) - 1u));

    float* outB = out + (size_t)b * MAXDET * 6;
    for (int q = t; q < MAXDET * 6; q += 1024) outB[q] = 0.0f;
    __syncthreads();

    if (keepme && rank < MAXDET) {
        int g = b * TOPK + t;
        float* r = outB + rank * 6;
        r[0] = g_bx1[g]; r[1] = g_by1[g]; r[2] = g_bx2[g]; r[3] = g_by2[g];
        r[4] = g_bsc[g]; r[5] = g_bcl[g];
    }
}

// ---------------------------------------------------------------------------
extern "C" void kernel_launch(void* const* d_in, const int* in_sizes, int n_in,
                              void* d_out, int out_size)
{
    const float* r0 = (const float*)d_in[0];
    const float* r1 = (const float*)d_in[1];
    const float* r2 = (const float*)d_in[2];
    const float* stride = (const float*)d_in[3];
    const float* ag = (const float*)d_in[4];
    float* out = (float*)d_out;

    int total = B * NPRED;
    zero_hist_kernel<<<B, NBINS>>>();
    score_kernel<<<(total + 255) / 256, 256>>>(r0, r1, r2);
    topk_select_kernel<<<B, 1024>>>();
    decode_kernel<<<B, 1024>>>(r0, r1, r2, stride, ag);
    mask_kernel<<<dim3(8, B), 256>>>();
    greedy_out_kernel<<<B, 1024>>>(out);
}

// round 8
// speedup vs baseline: 4.5501x; 1.3066x over previous
#include <cuda_runtime.h>
#include <cstdint>

#define B 64
#define NPRED 25200          // 3*(6400+1600+400) anchors*cells
#define TOPK 1024
#define MAXDET 300
#define CONF_THRES 0.25f
#define IOU_THRES 0.45f
#define NBINS 1024
#define CAP 4096             // smem candidate buffer (keys >= bin threshold)

// valid scores lie in (0.25, 1): fp32 bits in (0x3E800000, 0x3F800000)
#define BIN_BASE 0x3E800000u

__device__ unsigned long long g_keys[B * NPRED];   // (score_bits<<32)|(~idx)
__device__ unsigned long long g_top[B * TOPK];     // per-image sorted top-1024 keys
__device__ unsigned int       g_hist[B * NBINS];

// candidate SoA (decoded boxes for the 1024 selected per image)
__device__ float g_bx1[B * TOPK];
__device__ float g_by1[B * TOPK];
__device__ float g_bx2[B * TOPK];
__device__ float g_by2[B * TOPK];
__device__ float g_bar[B * TOPK];
__device__ float g_bsc[B * TOPK];
__device__ float g_bcl[B * TOPK];
__device__ unsigned g_active[B * 32];              // active bit per candidate

// suppression bitmatrix, WORD-MAJOR: g_mask[b][w][i] bit jj of row i at word w
// means: row i suppresses j = w*32 + jj (only j > i bits are set).
// Written only for i < 32*(w+1) (groups g <= w); rest is garbage, never read.
__device__ unsigned g_mask[B * 32 * TOPK];         // 8.4 MB

__device__ __forceinline__ float sigmoidf(float x) {
    return 1.0f / (1.0f + expf(-x));
}

// ---------------------------------------------------------------------------
// K0: zero per-image histograms
// ---------------------------------------------------------------------------
__global__ void zero_hist_kernel()
{
    g_hist[blockIdx.x * NBINS + threadIdx.x] = 0u;
}

// ---------------------------------------------------------------------------
// K1: per-candidate score -> sortable key + score-bin histogram
// ---------------------------------------------------------------------------
__global__ void score_kernel(const float* __restrict__ r0,
                             const float* __restrict__ r1,
                             const float* __restrict__ r2)
{
    int gid = blockIdx.x * blockDim.x + threadIdx.x;
    if (gid >= B * NPRED) return;
    int b = gid / NPRED;
    int p = gid - b * NPRED;

    const float* v;
    if (p < 19200)      v = r0 + (size_t)(b * 19200 + p) * 20;
    else if (p < 24000) v = r1 + (size_t)(b * 4800 + (p - 19200)) * 20;
    else                v = r2 + (size_t)(b * 1200 + (p - 24000)) * 20;

    const float4* v4 = (const float4*)v;
    float4 qa = v4[1];   // obj, cls0..2
    float4 qb = v4[2];
    float4 qc = v4[3];
    float4 qd = v4[4];

    float m = qa.y;
    m = fmaxf(m, qa.z); m = fmaxf(m, qa.w);
    m = fmaxf(m, qb.x); m = fmaxf(m, qb.y); m = fmaxf(m, qb.z); m = fmaxf(m, qb.w);
    m = fmaxf(m, qc.x); m = fmaxf(m, qc.y); m = fmaxf(m, qc.z); m = fmaxf(m, qc.w);
    m = fmaxf(m, qd.x); m = fmaxf(m, qd.y); m = fmaxf(m, qd.z); m = fmaxf(m, qd.w);

    float obj  = sigmoidf(qa.x);
    float best = obj * sigmoidf(m);
    bool valid = (obj > CONF_THRES) && (best > CONF_THRES);
    float score = valid ? best : 0.0f;

    if (valid) {
        unsigned bin = (__float_as_uint(score) - BIN_BASE) >> 14;
        atomicAdd(&g_hist[b * NBINS + bin], 1u);
    }

    unsigned long long key =
        ((unsigned long long)__float_as_uint(score) << 32) |
        (unsigned long long)(0xFFFFFFFFu - (unsigned)p);
    g_keys[gid] = key;
}

// ---------------------------------------------------------------------------
// K2: exact per-image top-1024 via radix-select + single bitonic sort
// ---------------------------------------------------------------------------
__device__ __forceinline__ void bitonic_sort_desc_1k(unsigned long long* a, int t)
{
    for (int k = 2; k <= 1024; k <<= 1) {
        for (int j = k >> 1; j > 0; j >>= 1) {
            int ixj = t ^ j;
            if (ixj > t) {
                unsigned long long u = a[t], w = a[ixj];
                bool desc = ((t & k) == 0);
                if ((u < w) == desc) { a[t] = w; a[ixj] = u; }
            }
            __syncthreads();
        }
    }
}

__device__ __forceinline__ void bitonic_merge_desc_1k(unsigned long long* a, int t)
{
    for (int j = 512; j > 0; j >>= 1) {
        int ixj = t ^ j;
        if (ixj > t) {
            unsigned long long u = a[t], w = a[ixj];
            if (u < w) { a[t] = w; a[ixj] = u; }
        }
        __syncthreads();
    }
}

__global__ __launch_bounds__(1024) void topk_select_kernel()
{
    __shared__ unsigned long long sBuf[CAP];         // 32 KB
    __shared__ unsigned int sA[NBINS], sBn[NBINS];   // 8 KB scan ping-pong
    __shared__ int sCut, sCount;

    int b = blockIdx.x;
    int t = threadIdx.x;
    const unsigned long long* k = g_keys + (size_t)b * NPRED;

    sA[t] = g_hist[b * NBINS + (NBINS - 1 - t)];
    if (t == 0) { sCut = 0; sCount = 0; }
    __syncthreads();

    unsigned int* src = sA;
    unsigned int* dst = sBn;
    for (int off = 1; off < NBINS; off <<= 1) {
        unsigned v = src[t] + ((t >= off) ? src[t - off] : 0u);
        dst[t] = v;
        __syncthreads();
        unsigned int* tmp = src; src = dst; dst = tmp;
    }
    {
        unsigned S     = src[NBINS - 1 - t];
        unsigned Snext = (t == NBINS - 1) ? 0u : src[NBINS - 2 - t];
        if (S >= TOPK && Snext < TOPK) sCut = t;
    }
    __syncthreads();
    int cutoff = sCut;
    unsigned long long thresh =
        ((unsigned long long)(BIN_BASE + ((unsigned)cutoff << 14))) << 32;

    const int NCHUNK = (NPRED + 1023) / 1024;   // 25
    for (int c = 0; c < NCHUNK; ++c) {
        int idx = c * 1024 + t;
        unsigned long long key = (idx < NPRED) ? k[idx] : 0ULL;
        if (key >= thresh) {
            int pos = atomicAdd(&sCount, 1);
            if (pos < CAP) sBuf[pos] = key;
        }
    }
    __syncthreads();
    int n = sCount;

    if (n <= CAP) {
        int P = TOPK;
        while (P < n) P <<= 1;
        for (int i = t; i < P; i += 1024)
            if (i >= n) sBuf[i] = 0ULL;
        __syncthreads();

        int E = P >> 10;
        for (int kk = 2; kk <= P; kk <<= 1) {
            for (int j = kk >> 1; j > 0; j >>= 1) {
                for (int e = 0; e < E; ++e) {
                    int i = e * 1024 + t;
                    int ixj = i ^ j;
                    if (ixj > i) {
                        unsigned long long u = sBuf[i], w = sBuf[ixj];
                        bool desc = ((i & kk) == 0);
                        if ((u < w) == desc) { sBuf[i] = w; sBuf[ixj] = u; }
                    }
                }
                __syncthreads();
            }
        }
        g_top[(size_t)b * TOPK + t] = sBuf[t];
    } else {
        unsigned long long* sTop = sBuf;
        unsigned long long* sCh  = sBuf + 1024;
        sTop[t] = k[t];
        __syncthreads();
        bitonic_sort_desc_1k(sTop, t);
        for (int c = 1; c < NCHUNK; ++c) {
            int idx = c * 1024 + t;
            sCh[t] = (idx < NPRED) ? k[idx] : 0ULL;
            __syncthreads();
            bitonic_sort_desc_1k(sCh, t);
            unsigned long long a = sTop[t];
            unsigned long long w = sCh[1023 - t];
            unsigned long long m = (a > w) ? a : w;
            __syncthreads();
            sTop[t] = m;
            __syncthreads();
            bitonic_merge_desc_1k(sTop, t);
        }
        g_top[(size_t)b * TOPK + t] = sTop[t];
    }
}

// ---------------------------------------------------------------------------
// K3a: decode the 1024 selected candidates per image -> global SoA
// ---------------------------------------------------------------------------
__global__ __launch_bounds__(1024) void decode_kernel(const float* __restrict__ r0,
                                                      const float* __restrict__ r1,
                                                      const float* __restrict__ r2,
                                                      const float* __restrict__ stride,
                                                      const float* __restrict__ ag)
{
    int b = blockIdx.x;
    int t = threadIdx.x;
    int g = b * TOPK + t;

    unsigned long long key = g_top[(size_t)g];
    float sc = __uint_as_float((unsigned)(key >> 32));
    unsigned p = 0xFFFFFFFFu - (unsigned)(key & 0xFFFFFFFFu);
    if (p >= NPRED) p = 0;

    const float* v;
    float s;
    int scale, a, gy, gx;
    if (p < 19200) {
        scale = 0; int l = p;
        a = l / 6400; int r = l - a * 6400; gy = r / 80; gx = r - gy * 80;
        v = r0 + (size_t)(b * 19200 + l) * 20; s = stride[0];
    } else if (p < 24000) {
        scale = 1; int l = p - 19200;
        a = l / 1600; int r = l - a * 1600; gy = r / 40; gx = r - gy * 40;
        v = r1 + (size_t)(b * 4800 + l) * 20; s = stride[1];
    } else {
        scale = 2; int l = p - 24000;
        a = l / 400; int r = l - a * 400; gy = r / 20; gx = r - gy * 20;
        v = r2 + (size_t)(b * 1200 + l) * 20; s = stride[2];
    }

    const float4* v4 = (const float4*)v;
    float4 q0 = v4[0];
    float4 qa = v4[1];
    float4 qb = v4[2];
    float4 qc = v4[3];
    float4 qd = v4[4];

    float s0 = sigmoidf(q0.x);
    float s1 = sigmoidf(q0.y);
    float s2 = sigmoidf(q0.z);
    float s3 = sigmoidf(q0.w);
    float cx = (s0 * 2.0f - 0.5f + (float)gx) * s;
    float cy = (s1 * 2.0f - 0.5f + (float)gy) * s;
    float tw = s2 * 2.0f;
    float th = s3 * 2.0f;
    float w = tw * tw * ag[scale * 6 + a * 2 + 0];
    float h = th * th * ag[scale * 6 + a * 2 + 1];

    float x1 = cx - w * 0.5f;
    float y1 = cy - h * 0.5f;
    float x2 = cx + w * 0.5f;
    float y2 = cy + h * 0.5f;

    float cls[15] = { qa.y, qa.z, qa.w, qb.x, qb.y, qb.z, qb.w,
                      qc.x, qc.y, qc.z, qc.w, qd.x, qd.y, qd.z, qd.w };
    float mv = cls[0]; int mc = 0;
#pragma unroll
    for (int c = 1; c < 15; ++c)
        if (cls[c] > mv) { mv = cls[c]; mc = c; }

    g_bx1[g] = x1; g_by1[g] = y1; g_bx2[g] = x2; g_by2[g] = y2;
    g_bar[g] = (x2 - x1) * (y2 - y1);
    g_bsc[g] = sc; g_bcl[g] = (float)mc;

    int act = (sc > CONF_THRES) ? 1 : 0;
    unsigned ballot = __ballot_sync(0xffffffffu, act);
    if ((t & 31) == 0) g_active[b * 32 + (t >> 5)] = ballot;
}

// ---------------------------------------------------------------------------
// K3b: suppression bitmatrix v2 — warp = row-group, word uniform per warp
// lane = row within group  ->  j-loads broadcast, stores coalesced (word-major)
// grid (4, B), 1024 threads. Warp->group map balances SMSP load (sum=132 each).
// ---------------------------------------------------------------------------
__global__ __launch_bounds__(1024) void mask_kernel()
{
    __shared__ float sx1[TOPK], sy1[TOPK], sx2[TOPK], sy2[TOPK], sar[TOPK];

    int b = blockIdx.y;
    int x = blockIdx.x;          // 0..3 word-range split
    int t = threadIdx.x;
    int lane = t & 31, w_id = t >> 5;
    int base = b * TOPK;

    sx1[t] = g_bx1[base + t];
    sy1[t] = g_by1[base + t];
    sx2[t] = g_bx2[base + t];
    sy2[t] = g_by2[base + t];
    sar[t] = g_bar[base + t];
    __syncthreads();

    // balanced group map: SMSP s gets groups {s,7-s,8+s,15-s,16+s,23-s,24+s,31-s}
    int s = w_id & 3, q = w_id >> 2;
    int g = 8 * (q >> 1) + ((q & 1) ? (7 - s) : s);

    int i = g * 32 + lane;
    float bx1 = sx1[i], by1 = sy1[i], bx2 = sx2[i], by2 = sy2[i], ba = sar[i];

    int cnt = 32 - g;
    int wlo = g + (cnt * x) / 4;
    int whi = g + (cnt * (x + 1)) / 4;

    for (int w = wlo; w < whi; ++w) {
        unsigned bits = 0;
#pragma unroll
        for (int jj = 0; jj < 32; ++jj) {
            int j = (w << 5) + jj;            // uniform across lanes -> broadcast
            float lx = fmaxf(bx1, sx1[j]);
            float ly = fmaxf(by1, sy1[j]);
            float rx = fminf(bx2, sx2[j]);
            float ry = fminf(by2, sy2[j]);
            float iw = fmaxf(rx - lx, 0.0f);
            float ih = fmaxf(ry - ly, 0.0f);
            float inter = iw * ih;
            // iou > T  <=>  inter > T * U   (U > 0 always)
            float U = ba + sar[j];
            U = U - inter;
            U = U + 1e-7f;
            if (inter > IOU_THRES * U) bits |= (1u << jj);
        }
        if (w == g) bits &= ~((2u << lane) - 1u);   // keep only j > i
        g_mask[(((size_t)(b * 32 + w)) << 10) + i] = bits;   // coalesced
    }
}

// ---------------------------------------------------------------------------
// K3c: greedy reduction v2 (group-serial, one shfl per 32 rows) + output
// lane L holds the column word L; per group g: lane g resolves its 32 rows
// locally (diag words), broadcasts kept mask, lanes > g batch-OR.
// ---------------------------------------------------------------------------
__global__ __launch_bounds__(1024) void greedy_out_kernel(float* __restrict__ out)
{
    __shared__ unsigned s_keepw[32];
    __shared__ int s_woff[32];

    int b = blockIdx.x;
    int t = threadIdx.x;
    int lane = t & 31, wid = t >> 5;

    if (wid == 0) {
        const unsigned* colp = g_mask + (((size_t)(b * 32 + lane)) << 10);
        unsigned activew = g_active[b * 32 + lane];
        unsigned removed = 0;
        unsigned wv[32], wn[32];

#pragma unroll
        for (int ii = 0; ii < 32; ++ii) wv[ii] = colp[ii];   // group 0 (all lanes valid)

#pragma unroll 1
        for (int g = 0; g < 32; ++g) {
            if (g < 31) {
#pragma unroll
                for (int ii = 0; ii < 32; ++ii)
                    wn[ii] = (lane >= g + 1) ? colp[(g + 1) * 32 + ii] : 0u;
            }

            unsigned keptm = 0;
            if (lane == g) {
                unsigned rem = removed;
#pragma unroll
                for (int ii = 0; ii < 32; ++ii) {
                    unsigned bit = 1u << ii;
                    if ((activew & bit) && !(rem & bit)) {
                        keptm |= bit;
                        rem |= wv[ii];
                    }
                }
                removed = rem;
                s_keepw[g] = keptm;
            }
            keptm = __shfl_sync(0xffffffffu, keptm, g);

            if (lane > g) {
                unsigned acc = 0;
#pragma unroll
                for (int ii = 0; ii < 32; ++ii)
                    if (keptm & (1u << ii)) acc |= wv[ii];
                removed |= acc;
            }
#pragma unroll
            for (int ii = 0; ii < 32; ++ii) wv[ii] = wn[ii];
        }
        // s_keepw[g] already holds active & ~removed per group:
        // a row is kept iff active and never suppressed when its turn came,
        // which is exactly the keptm computed in its group's serial pass.
    }
    __syncthreads();

    if (t == 0) {
        int acc = 0;
        for (int w = 0; w < 32; ++w) { s_woff[w] = acc; acc += __popc(s_keepw[w]); }
    }
    __syncthreads();

    int keepme = (s_keepw[wid] >> lane) & 1;
    int rank = s_woff[wid] + __popc(s_keepw[wid] & ((1u << lane) - 1u));

    float* outB = out + (size_t)b * MAXDET * 6;
    for (int q = t; q < MAXDET * 6; q += 1024) outB[q] = 0.0f;
    __syncthreads();

    if (keepme && rank < MAXDET) {
        int g = b * TOPK + t;
        float* r = outB + rank * 6;
        r[0] = g_bx1[g]; r[1] = g_by1[g]; r[2] = g_bx2[g]; r[3] = g_by2[g];
        r[4] = g_bsc[g]; r[5] = g_bcl[g];
    }
}

// ---------------------------------------------------------------------------
extern "C" void kernel_launch(void* const* d_in, const int* in_sizes, int n_in,
                              void* d_out, int out_size)
{
    const float* r0 = (const float*)d_in[0];
    const float* r1 = (const float*)d_in[1];
    const float* r2 = (const float*)d_in[2];
    const float* stride = (const float*)d_in[3];
    const float* ag = (const float*)d_in[4];
    float* out = (float*)d_out;

    int total = B * NPRED;
    zero_hist_kernel<<<B, NBINS>>>();
    score_kernel<<<(total + 255) / 256, 256>>>(r0, r1, r2);
    topk_select_kernel<<<B, 1024>>>();
    decode_kernel<<<B, 1024>>>(r0, r1, r2, stride, ag);
    mask_kernel<<<dim3(4, B), 1024>>>();
    greedy_out_kernel<<<B, 1024>>>(out);
}

// round 9
// speedup vs baseline: 4.6406x; 1.0199x over previous
#include <cuda_runtime.h>
#include <cstdint>

#define B 64
#define NPRED 25200          // 3*(6400+1600+400) anchors*cells
#define TOPK 1024
#define MAXDET 300
#define CONF_THRES 0.25f
#define IOU_THRES 0.45f
#define NBINS 1024
#define CAP 4096             // smem candidate buffer (keys >= bin threshold)

// valid scores lie in (0.25, 1): fp32 bits in (0x3E800000, 0x3F800000)
#define BIN_BASE 0x3E800000u

__device__ unsigned long long g_keys[B * NPRED];   // (score_bits<<32)|(~idx)
__device__ unsigned int       g_hist[B * NBINS];   // zero-init; re-zeroed by K2 tail

// candidate data (decoded boxes for the 1024 selected per image)
__device__ float4 g_box[B * TOPK];                 // x1,y1,x2,y2
__device__ float  g_bar[B * TOPK];
__device__ float  g_bsc[B * TOPK];
__device__ float  g_bcl[B * TOPK];
__device__ unsigned g_active[B * 32];

// suppression bitmatrix, WORD-MAJOR: g_mask[b][w][i] bit jj -> row i suppresses
// j = w*32+jj (j>i bits only). Valid only for i < 32*(w+1); rest never read.
__device__ unsigned g_mask[B * 32 * TOPK];         // 8.4 MB

__device__ __forceinline__ float sigmoidf(float x) {
    return 1.0f / (1.0f + expf(-x));
}

// ---------------------------------------------------------------------------
// K1: per-candidate score -> sortable key + score-bin histogram
// 2 records/thread, clamped tail for unconditional (batchable) loads
// ---------------------------------------------------------------------------
__device__ __forceinline__ void score_one(const float* __restrict__ r0,
                                          const float* __restrict__ r1,
                                          const float* __restrict__ r2,
                                          int b, int p, bool live)
{
    int pc = p < NPRED ? p : NPRED - 1;
    const float* v;
    if (pc < 19200)      v = r0 + (size_t)(b * 19200 + pc) * 20;
    else if (pc < 24000) v = r1 + (size_t)(b * 4800 + (pc - 19200)) * 20;
    else                 v = r2 + (size_t)(b * 1200 + (pc - 24000)) * 20;

    const float4* v4 = (const float4*)v;
    float4 qa = v4[1];   // obj, cls0..2
    float4 qb = v4[2];
    float4 qc = v4[3];
    float4 qd = v4[4];

    float m = qa.y;
    m = fmaxf(m, qa.z); m = fmaxf(m, qa.w);
    m = fmaxf(m, qb.x); m = fmaxf(m, qb.y); m = fmaxf(m, qb.z); m = fmaxf(m, qb.w);
    m = fmaxf(m, qc.x); m = fmaxf(m, qc.y); m = fmaxf(m, qc.z); m = fmaxf(m, qc.w);
    m = fmaxf(m, qd.x); m = fmaxf(m, qd.y); m = fmaxf(m, qd.z); m = fmaxf(m, qd.w);

    float obj  = sigmoidf(qa.x);
    float best = obj * sigmoidf(m);
    bool valid = (obj > CONF_THRES) && (best > CONF_THRES);
    float score = valid ? best : 0.0f;

    if (live) {
        if (valid) {
            unsigned bin = (__float_as_uint(score) - BIN_BASE) >> 14;
            atomicAdd(&g_hist[b * NBINS + bin], 1u);
        }
        unsigned long long key =
            ((unsigned long long)__float_as_uint(score) << 32) |
            (unsigned long long)(0xFFFFFFFFu - (unsigned)p);
        g_keys[(size_t)b * NPRED + p] = key;
    }
}

__global__ void score_kernel(const float* __restrict__ r0,
                             const float* __restrict__ r1,
                             const float* __restrict__ r2)
{
    int b  = blockIdx.y;
    int p0 = blockIdx.x * 512 + threadIdx.x;
    int p1 = p0 + 256;
    score_one(r0, r1, r2, b, p0, p0 < NPRED);
    score_one(r0, r1, r2, b, p1, p1 < NPRED);
}

// ---------------------------------------------------------------------------
// K2: radix-select + single bitonic sort + FUSED decode + hist re-zero
// ---------------------------------------------------------------------------
__device__ __forceinline__ void bitonic_sort_desc_1k(unsigned long long* a, int t)
{
    for (int k = 2; k <= 1024; k <<= 1) {
        for (int j = k >> 1; j > 0; j >>= 1) {
            int ixj = t ^ j;
            if (ixj > t) {
                unsigned long long u = a[t], w = a[ixj];
                bool desc = ((t & k) == 0);
                if ((u < w) == desc) { a[t] = w; a[ixj] = u; }
            }
            __syncthreads();
        }
    }
}

__device__ __forceinline__ void bitonic_merge_desc_1k(unsigned long long* a, int t)
{
    for (int j = 512; j > 0; j >>= 1) {
        int ixj = t ^ j;
        if (ixj > t) {
            unsigned long long u = a[t], w = a[ixj];
            if (u < w) { a[t] = w; a[ixj] = u; }
        }
        __syncthreads();
    }
}

__global__ __launch_bounds__(1024) void topk_decode_kernel(
    const float* __restrict__ r0,
    const float* __restrict__ r1,
    const float* __restrict__ r2,
    const float* __restrict__ stride,
    const float* __restrict__ ag)
{
    __shared__ unsigned long long sBuf[CAP];         // 32 KB
    __shared__ unsigned int sA[NBINS], sBn[NBINS];   // 8 KB scan ping-pong
    __shared__ int sCut, sCount;

    int b = blockIdx.x;
    int t = threadIdx.x;
    int lane = t & 31;
    const unsigned long long* k = g_keys + (size_t)b * NPRED;

    sA[t] = g_hist[b * NBINS + (NBINS - 1 - t)];
    if (t == 0) { sCut = 0; sCount = 0; }
    __syncthreads();

    unsigned int* src = sA;
    unsigned int* dst = sBn;
    for (int off = 1; off < NBINS; off <<= 1) {
        unsigned v = src[t] + ((t >= off) ? src[t - off] : 0u);
        dst[t] = v;
        __syncthreads();
        unsigned int* tmp = src; src = dst; dst = tmp;
    }
    {
        unsigned S     = src[NBINS - 1 - t];
        unsigned Snext = (t == NBINS - 1) ? 0u : src[NBINS - 2 - t];
        if (S >= TOPK && Snext < TOPK) sCut = t;
    }
    __syncthreads();
    int cutoff = sCut;
    unsigned long long thresh =
        ((unsigned long long)(BIN_BASE + ((unsigned)cutoff << 14))) << 32;

    // compact keys >= thresh (warp-aggregated atomic; order irrelevant pre-sort)
    const int NCHUNK = (NPRED + 1023) / 1024;   // 25
    for (int c = 0; c < NCHUNK; ++c) {
        int idx = c * 1024 + t;
        unsigned long long key = (idx < NPRED) ? k[idx] : 0ULL;
        bool pred = key >= thresh;
        unsigned m = __ballot_sync(0xffffffffu, pred);
        int nset = __popc(m);
        int basepos = 0;
        if (lane == 0 && nset) basepos = atomicAdd(&sCount, nset);
        basepos = __shfl_sync(0xffffffffu, basepos, 0);
        int pos = basepos + __popc(m & ((1u << lane) - 1u));
        if (pred && pos < CAP) sBuf[pos] = key;
    }
    __syncthreads();
    int n = sCount;

    if (n <= CAP) {
        int P = TOPK;
        while (P < n) P <<= 1;
        for (int i = t; i < P; i += 1024)
            if (i >= n) sBuf[i] = 0ULL;
        __syncthreads();

        int E = P >> 10;
        for (int kk = 2; kk <= P; kk <<= 1) {
            for (int j = kk >> 1; j > 0; j >>= 1) {
                for (int e = 0; e < E; ++e) {
                    int i = e * 1024 + t;
                    int ixj = i ^ j;
                    if (ixj > i) {
                        unsigned long long u = sBuf[i], w = sBuf[ixj];
                        bool desc = ((i & kk) == 0);
                        if ((u < w) == desc) { sBuf[i] = w; sBuf[ixj] = u; }
                    }
                }
                __syncthreads();
            }
        }
    } else {
        // fallback (never expected): exhaustive chunked merge top-k into sBuf
        unsigned long long* sTop = sBuf;
        unsigned long long* sCh  = sBuf + 1024;
        sTop[t] = k[t];
        __syncthreads();
        bitonic_sort_desc_1k(sTop, t);
        for (int c = 1; c < NCHUNK; ++c) {
            int idx = c * 1024 + t;
            sCh[t] = (idx < NPRED) ? k[idx] : 0ULL;
            __syncthreads();
            bitonic_sort_desc_1k(sCh, t);
            unsigned long long a = sTop[t];
            unsigned long long w = sCh[1023 - t];
            unsigned long long m = (a > w) ? a : w;
            __syncthreads();
            sTop[t] = m;
            __syncthreads();
            bitonic_merge_desc_1k(sTop, t);
        }
    }

    // ---- fused decode of the sorted top-1024 ----
    unsigned long long key = sBuf[t];
    float sc = __uint_as_float((unsigned)(key >> 32));
    unsigned p = 0xFFFFFFFFu - (unsigned)(key & 0xFFFFFFFFu);
    if (p >= NPRED) p = 0;   // zero-padded keys

    const float* v;
    float s;
    int scale, a, gy, gx;
    if (p < 19200) {
        scale = 0; int l = p;
        a = l / 6400; int r = l - a * 6400; gy = r / 80; gx = r - gy * 80;
        v = r0 + (size_t)(b * 19200 + l) * 20; s = stride[0];
    } else if (p < 24000) {
        scale = 1; int l = p - 19200;
        a = l / 1600; int r = l - a * 1600; gy = r / 40; gx = r - gy * 40;
        v = r1 + (size_t)(b * 4800 + l) * 20; s = stride[1];
    } else {
        scale = 2; int l = p - 24000;
        a = l / 400; int r = l - a * 400; gy = r / 20; gx = r - gy * 20;
        v = r2 + (size_t)(b * 1200 + l) * 20; s = stride[2];
    }

    const float4* v4 = (const float4*)v;
    float4 q0 = v4[0];
    float4 qa = v4[1];
    float4 qb = v4[2];
    float4 qc = v4[3];
    float4 qd = v4[4];

    float s0 = sigmoidf(q0.x);
    float s1 = sigmoidf(q0.y);
    float s2 = sigmoidf(q0.z);
    float s3 = sigmoidf(q0.w);
    float cx = (s0 * 2.0f - 0.5f + (float)gx) * s;
    float cy = (s1 * 2.0f - 0.5f + (float)gy) * s;
    float tw = s2 * 2.0f;
    float th = s3 * 2.0f;
    float w = tw * tw * ag[scale * 6 + a * 2 + 0];
    float h = th * th * ag[scale * 6 + a * 2 + 1];

    float x1 = cx - w * 0.5f;
    float y1 = cy - h * 0.5f;
    float x2 = cx + w * 0.5f;
    float y2 = cy + h * 0.5f;

    float cls[15] = { qa.y, qa.z, qa.w, qb.x, qb.y, qb.z, qb.w,
                      qc.x, qc.y, qc.z, qc.w, qd.x, qd.y, qd.z, qd.w };
    float mv = cls[0]; int mc = 0;
#pragma unroll
    for (int c = 1; c < 15; ++c)
        if (cls[c] > mv) { mv = cls[c]; mc = c; }

    int g = b * TOPK + t;
    g_box[g] = make_float4(x1, y1, x2, y2);
    g_bar[g] = (x2 - x1) * (y2 - y1);
    g_bsc[g] = sc; g_bcl[g] = (float)mc;

    int act = (sc > CONF_THRES) ? 1 : 0;
    unsigned ballot = __ballot_sync(0xffffffffu, act);
    if (lane == 0) g_active[b * 32 + (t >> 5)] = ballot;

    // ---- re-zero histogram for the next call (last reader of g_hist) ----
    g_hist[b * NBINS + t] = 0u;
}

// ---------------------------------------------------------------------------
// K3b: suppression bitmatrix — warp = row-group, word uniform per warp
// float4 box smem -> 1 LDS.128 + 1 LDS per pair; word-major coalesced stores
// ---------------------------------------------------------------------------
__global__ __launch_bounds__(1024) void mask_kernel()
{
    __shared__ float4 sbox[TOPK];
    __shared__ float  sar[TOPK];

    int b = blockIdx.y;
    int x = blockIdx.x;          // 0..3 word-range split
    int t = threadIdx.x;
    int lane = t & 31, w_id = t >> 5;
    int base = b * TOPK;

    sbox[t] = g_box[base + t];
    sar[t]  = g_bar[base + t];
    __syncthreads();

    // balanced group map: SMSP s gets groups {s,7-s,8+s,15-s,16+s,23-s,24+s,31-s}
    int s = w_id & 3, q = w_id >> 2;
    int g = 8 * (q >> 1) + ((q & 1) ? (7 - s) : s);

    int i = g * 32 + lane;
    float4 bi = sbox[i];
    float ba = sar[i];

    int cnt = 32 - g;
    int wlo = g + (cnt * x) / 4;
    int whi = g + (cnt * (x + 1)) / 4;

    for (int w = wlo; w < whi; ++w) {
        unsigned bits = 0;
#pragma unroll
        for (int jj = 0; jj < 32; ++jj) {
            int j = (w << 5) + jj;            // uniform across lanes -> broadcast
            float4 bj = sbox[j];
            float aj = sar[j];
            float lx = fmaxf(bi.x, bj.x);
            float ly = fmaxf(bi.y, bj.y);
            float rx = fminf(bi.z, bj.z);
            float ry = fminf(bi.w, bj.w);
            float iw = fmaxf(rx - lx, 0.0f);
            float ih = fmaxf(ry - ly, 0.0f);
            float inter = iw * ih;
            // iou > T  <=>  inter > T * U   (U > 0 always)
            float U = ba + aj;
            U = U - inter;
            U = U + 1e-7f;
            if (inter > IOU_THRES * U) bits |= (1u << jj);
        }
        if (w == g) bits &= ~((2u << lane) - 1u);   // keep only j > i
        g_mask[(((size_t)(b * 32 + w)) << 10) + i] = bits;   // coalesced
    }
}

// ---------------------------------------------------------------------------
// K3c: greedy reduction (group-serial, one shfl per 32 rows) + output
// ---------------------------------------------------------------------------
__global__ __launch_bounds__(1024) void greedy_out_kernel(float* __restrict__ out)
{
    __shared__ unsigned s_keepw[32];
    __shared__ int s_woff[32];

    int b = blockIdx.x;
    int t = threadIdx.x;
    int lane = t & 31, wid = t >> 5;

    if (wid == 0) {
        const unsigned* colp = g_mask + (((size_t)(b * 32 + lane)) << 10);
        unsigned activew = g_active[b * 32 + lane];
        unsigned removed = 0;
        unsigned wv[32], wn[32];

#pragma unroll
        for (int ii = 0; ii < 32; ++ii) wv[ii] = colp[ii];

#pragma unroll 1
        for (int g = 0; g < 32; ++g) {
            if (g < 31) {
#pragma unroll
                for (int ii = 0; ii < 32; ++ii)
                    wn[ii] = (lane >= g + 1) ? colp[(g + 1) * 32 + ii] : 0u;
            }

            unsigned keptm = 0;
            if (lane == g) {
                unsigned rem = removed;
#pragma unroll
                for (int ii = 0; ii < 32; ++ii) {
                    unsigned bit = 1u << ii;
                    if ((activew & bit) && !(rem & bit)) {
                        keptm |= bit;
                        rem |= wv[ii];
                    }
                }
                removed = rem;
                s_keepw[g] = keptm;
            }
            keptm = __shfl_sync(0xffffffffu, keptm, g);

            if (lane > g) {
                unsigned acc = 0;
#pragma unroll
                for (int ii = 0; ii < 32; ++ii)
                    if (keptm & (1u << ii)) acc |= wv[ii];
                removed |= acc;
            }
#pragma unroll
            for (int ii = 0; ii < 32; ++ii) wv[ii] = wn[ii];
        }
    }
    __syncthreads();

    if (t == 0) {
        int acc = 0;
        for (int w = 0; w < 32; ++w) { s_woff[w] = acc; acc += __popc(s_keepw[w]); }
    }
    __syncthreads();

    int keepme = (s_keepw[wid] >> lane) & 1;
    int rank = s_woff[wid] + __popc(s_keepw[wid] & ((1u << lane) - 1u));

    float* outB = out + (size_t)b * MAXDET * 6;
    for (int q = t; q < MAXDET * 6; q += 1024) outB[q] = 0.0f;
    __syncthreads();

    if (keepme && rank < MAXDET) {
        int g = b * TOPK + t;
        float4 bx = g_box[g];
        float* r = outB + rank * 6;
        r[0] = bx.x; r[1] = bx.y; r[2] = bx.z; r[3] = bx.w;
        r[4] = g_bsc[g]; r[5] = g_bcl[g];
    }
}

// ---------------------------------------------------------------------------
extern "C" void kernel_launch(void* const* d_in, const int* in_sizes, int n_in,
                              void* d_out, int out_size)
{
    const float* r0 = (const float*)d_in[0];
    const float* r1 = (const float*)d_in[1];
    const float* r2 = (const float*)d_in[2];
    const float* stride = (const float*)d_in[3];
    const float* ag = (const float*)d_in[4];
    float* out = (float*)d_out;

    score_kernel<<<dim3((NPRED + 511) / 512, B), 256>>>(r0, r1, r2);
    topk_decode_kernel<<<B, 1024>>>(r0, r1, r2, stride, ag);
    mask_kernel<<<dim3(4, B), 1024>>>();
    greedy_out_kernel<<<B, 1024>>>(out);
}